// round 12
// baseline (speedup 1.0000x reference)
#include <cuda_runtime.h>
#include <math.h>
#include <stdint.h>

#define NEXP     8
#define HDIM     4096
#define WARPS    16
#define THREADS  512
#define BLOCKS   152
#define NWARP    (BLOCKS * WARPS)     // 2432
#define NTOK     16384
#define NGRP     (NTOK / 4)           // 4096 token-groups (4 tokens each)
#define NUNIT    (NGRP * 4)           // 16384 (group, K-quarter) units
#define H4       (HDIM / 4)           // 1024 float4 per row
#define UITER    8                    // k-iters per unit (quarter-K)
#define NSLOT    3

#define SW_BYTES (NEXP * HDIM * 4)            // 128 KB weights
#define SLOT_B   (4 * 512)                    // 2 KB per slot
#define WBUF_B   (NSLOT * SLOT_B)             // 6 KB per warp
#define SMEM_B   (SW_BYTES + WARPS * WBUF_B)  // 224 KB

// cross-warp combination scratch (static device globals: allowed, zero-init)
__device__ float g_part[NGRP][4][32];
__device__ int   g_cnt[NGRP];

// ---- cp.async primitives (16B, L1-bypass) ----
#define CP_ASYNC16(dst, src) \
    asm volatile("cp.async.cg.shared.global [%0], [%1], 16;" \
                 :: "r"(dst), "l"(src) : "memory")
#define CP_COMMIT() asm volatile("cp.async.commit_group;" ::: "memory")
#define CP_WAIT2()  asm volatile("cp.async.wait_group 2;"  ::: "memory")

__global__ __launch_bounds__(THREADS, 1)
void moe_router_kernel(const float* __restrict__ hs,
                       const float* __restrict__ rw,
                       float* __restrict__ out)
{
    extern __shared__ float sm[];
    float4* sw4 = reinterpret_cast<float4*>(sm);

    // Stage router weights into smem (coalesced, once per block)
    {
        const float4* rw4 = reinterpret_cast<const float4*>(rw);
        #pragma unroll
        for (int i = threadIdx.x; i < NEXP * H4; i += THREADS)
            sw4[i] = rw4[i];
    }
    __syncthreads();

    const int lane = threadIdx.x & 31;
    const int wid  = threadIdx.x >> 5;

    // This warp's private 3-slot hidden ring buffer
    const uint32_t smb = (uint32_t)__cvta_generic_to_shared(sm);
    const uint32_t hb  = smb + SW_BYTES + wid * WBUF_B;
    const float4*  hgen = reinterpret_cast<const float4*>(
        reinterpret_cast<const char*>(sm) + SW_BYTES + wid * WBUF_B);

    // Interleaved mapping: 7-unit warps spread across all SMs
    const int gwarp = wid * gridDim.x + blockIdx.x;
    const int nu    = (NUNIT - gwarp + NWARP - 1) / NWARP;   // 6 or 7 units
    const int total_j = nu * UITER;

    float* out_w = out;                     // [NTOK, 2] top-k weights
    float* out_i = out + (size_t)NTOK * 2;  // [NTOK, 2] indices (as float)
    float* out_l = out + (size_t)NTOK * 4;  // [NTOK, 8] raw logits

    // current-unit state (compute side)
    int u_cur = gwarp;
    int g_cur = u_cur >> 2;
    int q_cur = u_cur & 3;
    const float* hs_cur = hs + (size_t)g_cur * 4 * HDIM;

    // prefetch-side state: next target is linear iter j=3 (unit 0, iter 3)
    int pf_u = gwarp, pf_i = 3, pf_q = q_cur;
    const float* pf_hs = hs_cur;

    // Prologue: fill slots 0..2 = iters 0..2 of unit 0 (UITER=8 > 3 always)
    #pragma unroll
    for (int s = 0; s < NSLOT; s++) {
        #pragma unroll
        for (int t = 0; t < 4; t++)
            CP_ASYNC16(hb + s * SLOT_B + t * 512 + lane * 16,
                       hs_cur + (size_t)t * HDIM + q_cur * 1024 + (s * 32 + lane) * 4);
        CP_COMMIT();
    }

    float v[32];
    #pragma unroll
    for (int x = 0; x < 32; x++) v[x] = 0.0f;

    uint32_t slotoff = 0;
    #pragma unroll 1
    for (int j = 0; j < total_j; j++) {
        const int i = j & (UITER - 1);
        CP_WAIT2();                           // linear group j complete

        const int kk = q_cur * 256 + i * 32 + lane;   // float4 idx in weights
        float4 w[NEXP];
        #pragma unroll
        for (int e = 0; e < NEXP; e++)
            w[e] = sw4[e * H4 + kk];

        float4 h[4];
        #pragma unroll
        for (int t = 0; t < 4; t++)
            h[t] = hgen[(slotoff >> 4) + t * 32 + lane];

        // Continuous refill: target linear iter j+3 (may cross unit boundary)
        if (j + 3 < total_j) {
            #pragma unroll
            for (int t = 0; t < 4; t++)
                CP_ASYNC16(hb + slotoff + t * 512 + lane * 16,
                           pf_hs + (size_t)t * HDIM + pf_q * 1024 + (pf_i * 32 + lane) * 4);
            if (++pf_i == UITER) {
                pf_i = 0;
                pf_u += NWARP;
                pf_q  = pf_u & 3;
                pf_hs = hs + (size_t)(pf_u >> 2) * 4 * HDIM;
            }
        }
        CP_COMMIT();                          // exact group counting

        #pragma unroll
        for (int t = 0; t < 4; t++) {
            #pragma unroll
            for (int e = 0; e < NEXP; e++) {
                v[t * NEXP + e] = fmaf(h[t].x, w[e].x, v[t * NEXP + e]);
                v[t * NEXP + e] = fmaf(h[t].y, w[e].y, v[t * NEXP + e]);
                v[t * NEXP + e] = fmaf(h[t].z, w[e].z, v[t * NEXP + e]);
                v[t * NEXP + e] = fmaf(h[t].w, w[e].w, v[t * NEXP + e]);
            }
        }

        slotoff = (slotoff == (NSLOT - 1) * SLOT_B) ? 0u : slotoff + SLOT_B;

        if (i == UITER - 1) {
            // ---- unit epilogue: reduce, publish quarter, maybe finalize ----
            #pragma unroll
            for (int o = 16; o >= 1; o >>= 1) {
                const bool up = (lane & o) != 0;
                #pragma unroll
                for (int jj = 0; jj < o; jj++) {
                    const float give = up ? v[jj] : v[jj + o];
                    const float keep = up ? v[jj + o] : v[jj];
                    const float recv = __shfl_xor_sync(0xffffffffu, give, o);
                    v[jj] = keep + recv;
                }
            }
            // v[0] = quarter-partial for (token g*4 + (lane>>3), expert lane&7)
            g_part[g_cur][q_cur][lane] = v[0];
            __threadfence();
            int old = 0;
            if (lane == 0) old = atomicAdd(&g_cnt[g_cur], 1);
            old = __shfl_sync(0xffffffffu, old, 0);

            if (old == 3) {                   // last quarter: finalize group
                __threadfence();
                const float s0 = __ldcg(&g_part[g_cur][0][lane]);
                const float s1 = __ldcg(&g_part[g_cur][1][lane]);
                const float s2 = __ldcg(&g_part[g_cur][2][lane]);
                const float s3 = __ldcg(&g_part[g_cur][3][lane]);
                const float logit = (s0 + s1) + (s2 + s3);   // fixed order
                const size_t t0 = (size_t)g_cur * 4;
                const int sub = lane & 7;

                out_l[t0 * NEXP + lane] = logit;   // coalesced 128B

                float bv = logit; int bi = sub;
                #pragma unroll
                for (int o = 4; o >= 1; o >>= 1) {
                    const float ov = __shfl_xor_sync(0xffffffffu, bv, o);
                    const int   oi = __shfl_xor_sync(0xffffffffu, bi, o);
                    if (ov > bv || (ov == bv && oi < bi)) { bv = ov; bi = oi; }
                }
                float sv = (sub == bi) ? -INFINITY : logit; int si = sub;
                #pragma unroll
                for (int o = 4; o >= 1; o >>= 1) {
                    const float ov = __shfl_xor_sync(0xffffffffu, sv, o);
                    const int   oi = __shfl_xor_sync(0xffffffffu, si, o);
                    if (ov > sv || (ov == sv && oi < si)) { sv = ov; si = oi; }
                }

                if (sub == 0) {
                    const size_t tok = t0 + (lane >> 3);
                    const float e2 = __expf(sv - bv);
                    const float r  = 1.0f / (1.0f + e2);
                    out_w[tok * 2 + 0] = r;
                    out_w[tok * 2 + 1] = e2 * r;
                    out_i[tok * 2 + 0] = (float)bi;
                    out_i[tok * 2 + 1] = (float)si;
                }
                if (lane == 0) g_cnt[g_cur] = 0;   // self-reset for next replay
            }

            // reset accumulators and advance to next unit
            #pragma unroll
            for (int x = 0; x < 32; x++) v[x] = 0.0f;
            if (j + 1 < total_j) {
                u_cur += NWARP;
                g_cur  = u_cur >> 2;
                q_cur  = u_cur & 3;
                hs_cur = hs + (size_t)g_cur * 4 * HDIM;
            }
        }
    }
}

extern "C" void kernel_launch(void* const* d_in, const int* in_sizes, int n_in,
                              void* d_out, int out_size)
{
    const float* hs = (const float*)d_in[0];   // hidden_states [4,4096,4096] f32
    const float* rw = (const float*)d_in[1];   // router_weight [8,4096] f32
    float* out = (float*)d_out;

    (void)in_sizes; (void)n_in; (void)out_size;

    cudaFuncSetAttribute(moe_router_kernel,
                         cudaFuncAttributeMaxDynamicSharedMemorySize, SMEM_B);

    moe_router_kernel<<<BLOCKS, THREADS, SMEM_B>>>(hs, rw, out);
}

// round 14
// speedup vs baseline: 1.0497x; 1.0497x over previous
#include <cuda_runtime.h>
#include <math.h>
#include <stdint.h>

#define NEXP     8
#define HDIM     4096
#define WARPS    16
#define THREADS  512
#define BLOCKS   152
#define NWARP    (BLOCKS * WARPS)     // 2432
#define NTOK     16384
#define H4       (HDIM / 4)           // 1024 float4 per row
#define KITERS   (H4 / 32)            // 32 k-iterations
#define NSLOT    3
// one group per warp: first RBIG warps own 7 tokens, rest own 6
#define TOK_BIG   7
#define TOK_SMALL 6
#define RBIG      (NTOK - TOK_SMALL * NWARP)   // 1792

#define SLOT_B   (TOK_BIG * 512)               // 3584 B per slot (sized for 7)
#define WBUF_B   (NSLOT * SLOT_B)              // 10752 B per warp
#define SMEM_B   (WARPS * WBUF_B)              // 168 KB total (NO weights in smem)

// ---- cp.async primitives (16B, .cg = L1-bypass; keeps L1 for weights) ----
#define CP_ASYNC16(dst, src) \
    asm volatile("cp.async.cg.shared.global [%0], [%1], 16;" \
                 :: "r"(dst), "l"(src) : "memory")
#define CP_COMMIT() asm volatile("cp.async.commit_group;" ::: "memory")
#define CP_WAIT2()  asm volatile("cp.async.wait_group 2;"  ::: "memory")

template<int TOKN>
__device__ __forceinline__ void process_warp(size_t t0, int lane,
                                             uint32_t hb, const float4* hgen,
                                             const float* __restrict__ hs,
                                             const float4* __restrict__ rw4,
                                             float* __restrict__ out_w,
                                             float* __restrict__ out_i,
                                             float* __restrict__ out_l)
{
    const float* hsrow = hs + t0 * HDIM;

    float acc[TOKN][NEXP];
    #pragma unroll
    for (int t = 0; t < TOKN; t++)
        #pragma unroll
        for (int e = 0; e < NEXP; e++)
            acc[t][e] = 0.0f;

    // Prologue: async-fill slots 0,1,2 (iters 0,1,2)
    #pragma unroll
    for (int s = 0; s < NSLOT; s++) {
        #pragma unroll
        for (int t = 0; t < TOKN; t++)
            CP_ASYNC16(hb + s * SLOT_B + t * 512 + lane * 16,
                       hsrow + (size_t)t * HDIM + (s * 32 + lane) * 4);
        CP_COMMIT();
    }

    uint32_t slotoff = 0;
    #pragma unroll 1
    for (int i = 0; i < KITERS; i++) {
        CP_WAIT2();                          // iter i's group complete

        // weights straight from L1 (128 KB resident; hidden bypasses L1)
        const int kk = i * 32 + lane;
        float4 w[NEXP];
        #pragma unroll
        for (int e = 0; e < NEXP; e++)
            w[e] = __ldg(&rw4[e * H4 + kk]);

        // READ the slot into registers BEFORE refilling it (race fix vs R13)
        float4 h[TOKN];
        #pragma unroll
        for (int t = 0; t < TOKN; t++)
            h[t] = hgen[(slotoff >> 4) + t * 32 + lane];

        // refill this slot for iter i+NSLOT
        if (i + NSLOT < KITERS) {
            const int kf = (i + NSLOT) * 32 + lane;
            #pragma unroll
            for (int t = 0; t < TOKN; t++)
                CP_ASYNC16(hb + slotoff + t * 512 + lane * 16,
                           hsrow + (size_t)t * HDIM + kf * 4);
        }
        CP_COMMIT();                         // exact group counting

        #pragma unroll
        for (int t = 0; t < TOKN; t++) {
            #pragma unroll
            for (int e = 0; e < NEXP; e++) {
                acc[t][e] = fmaf(h[t].x, w[e].x, acc[t][e]);
                acc[t][e] = fmaf(h[t].y, w[e].y, acc[t][e]);
                acc[t][e] = fmaf(h[t].z, w[e].z, acc[t][e]);
                acc[t][e] = fmaf(h[t].w, w[e].w, acc[t][e]);
            }
        }

        slotoff = (slotoff == (NSLOT - 1) * SLOT_B) ? 0u : slotoff + SLOT_B;
    }

    // Butterfly reduction (once per warp per kernel — amortized)
    #pragma unroll
    for (int off = 16; off > 0; off >>= 1) {
        #pragma unroll
        for (int t = 0; t < TOKN; t++)
            #pragma unroll
            for (int e = 0; e < NEXP; e++)
                acc[t][e] += __shfl_xor_sync(0xffffffffu, acc[t][e], off);
    }

    // Lanes 0..TOKN-1: one token each — top-2 + renorm + writes
    if (lane < TOKN) {
        float l[NEXP];
        #pragma unroll
        for (int t = 0; t < TOKN; t++) {
            if (lane == t) {
                #pragma unroll
                for (int e = 0; e < NEXP; e++) l[e] = acc[t][e];
            }
        }

        const size_t tok = t0 + lane;

        // argmax (ties -> lowest index, matching jax.lax.top_k)
        int   i1 = 0; float v1 = l[0];
        #pragma unroll
        for (int e = 1; e < NEXP; e++)
            if (l[e] > v1) { v1 = l[e]; i1 = e; }
        int   i2 = -1; float v2 = -INFINITY;
        #pragma unroll
        for (int e = 0; e < NEXP; e++)
            if (e != i1 && l[e] > v2) { v2 = l[e]; i2 = e; }

        // renormalized top-2 softmax weights
        const float e2 = __expf(v2 - v1);
        const float r  = 1.0f / (1.0f + e2);

        out_w[tok * 2 + 0] = r;
        out_w[tok * 2 + 1] = e2 * r;
        out_i[tok * 2 + 0] = (float)i1;
        out_i[tok * 2 + 1] = (float)i2;
        #pragma unroll
        for (int e = 0; e < NEXP; e++)
            out_l[tok * NEXP + e] = l[e];
    }
}

__global__ __launch_bounds__(THREADS, 1)
void moe_router_kernel(const float* __restrict__ hs,
                       const float* __restrict__ rw,
                       float* __restrict__ out)
{
    extern __shared__ float sm[];            // hidden ring buffers only

    const int lane = threadIdx.x & 31;
    const int wid  = threadIdx.x >> 5;

    const uint32_t smb = (uint32_t)__cvta_generic_to_shared(sm);
    const uint32_t hb  = smb + wid * WBUF_B;
    const float4*  hgen = reinterpret_cast<const float4*>(
        reinterpret_cast<const char*>(sm) + wid * WBUF_B);

    // Interleaved mapping: 7-token warps spread across all SMs
    const int gwarp = wid * gridDim.x + blockIdx.x;

    const float4* rw4 = reinterpret_cast<const float4*>(rw);

    float* out_w = out;                     // [NTOK, 2] top-k weights
    float* out_i = out + (size_t)NTOK * 2;  // [NTOK, 2] indices (as float)
    float* out_l = out + (size_t)NTOK * 4;  // [NTOK, 8] raw logits

    // One group per warp: warps [0, RBIG) own 7 tokens, the rest own 6.
    if (gwarp < RBIG) {
        const size_t t0 = (size_t)gwarp * TOK_BIG;
        process_warp<TOK_BIG>(t0, lane, hb, hgen, hs, rw4, out_w, out_i, out_l);
    } else {
        const size_t t0 = (size_t)RBIG * TOK_BIG
                        + (size_t)(gwarp - RBIG) * TOK_SMALL;
        process_warp<TOK_SMALL>(t0, lane, hb, hgen, hs, rw4, out_w, out_i, out_l);
    }
}

extern "C" void kernel_launch(void* const* d_in, const int* in_sizes, int n_in,
                              void* d_out, int out_size)
{
    const float* hs = (const float*)d_in[0];   // hidden_states [4,4096,4096] f32
    const float* rw = (const float*)d_in[1];   // router_weight [8,4096] f32
    float* out = (float*)d_out;

    (void)in_sizes; (void)n_in; (void)out_size;

    cudaFuncSetAttribute(moe_router_kernel,
                         cudaFuncAttributeMaxDynamicSharedMemorySize, SMEM_B);

    moe_router_kernel<<<BLOCKS, THREADS, SMEM_B>>>(hs, rw, out);
}